// round 2
// baseline (speedup 1.0000x reference)
#include <cuda_runtime.h>
#include <stdint.h>

// BagEmbedding: out[b,l,:] = sum_{k<50, X[b,l,k]!=0} W[X[b,l,k], :]
// X: (64,128,50) int32  -> d_in[0]
// W: (100000,128) fp32  -> d_in[1]
// out: (64,128,128) fp32
//
// One warp per output row (8192 rows). Each lane accumulates a float4
// (4 of the 128 embed dims). 50 independent LDG.128 gathers per lane,
// unrolled for MLP; W fits in L2 so steady-state is L2-BW bound.

#define NB_WORDS 50
#define EMBED    128
#define ROWS     (64 * 128)   // 8192

__global__ __launch_bounds__(256) void bag_embedding_kernel(
    const int* __restrict__ X,
    const float4* __restrict__ W4,   // W viewed as rows of 32 float4
    float4* __restrict__ out4)
{
    const int warp_id = (blockIdx.x * blockDim.x + threadIdx.x) >> 5;
    const int lane    = threadIdx.x & 31;
    if (warp_id >= ROWS) return;

    const int* __restrict__ xp = X + warp_id * NB_WORDS;

    // Phase 1: hoist all 50 indices into registers (warp-uniform,
    // L1-broadcast, line-sequential). Removes the dependent index load
    // from each gather's critical path and lets ptxas front-batch.
    int idx[NB_WORDS];
    #pragma unroll
    for (int k = 0; k < NB_WORDS; ++k) idx[k] = __ldg(xp + k);

    float4 acc = make_float4(0.f, 0.f, 0.f, 0.f);

    // Phase 2: 50 independent gathers, unrolled for MLP.
    #pragma unroll 10
    for (int k = 0; k < NB_WORDS; ++k) {
        if (idx[k] != 0) {                        // padding row (W[0]==0 anyway)
            const float4 v = __ldg(W4 + (size_t)idx[k] * (EMBED / 4) + lane);
            acc.x += v.x; acc.y += v.y; acc.z += v.z; acc.w += v.w;
        }
    }

    out4[(size_t)warp_id * (EMBED / 4) + lane] = acc;
}

extern "C" void kernel_launch(void* const* d_in, const int* in_sizes, int n_in,
                              void* d_out, int out_size)
{
    const int*    X = (const int*)d_in[0];
    const float4* W = (const float4*)d_in[1];
    float4*     out = (float4*)d_out;

    // 8192 warps -> 256 threads/block (8 warps) -> 1024 blocks
    const int threads = 256;
    const int blocks  = (ROWS * 32) / threads;
    bag_embedding_kernel<<<blocks, threads>>>(X, W, out);
}

// round 3
// speedup vs baseline: 1.4337x; 1.4337x over previous
#include <cuda_runtime.h>
#include <stdint.h>

// BagEmbedding: out[b,l,:] = sum_{k<50} W[X[b,l,k], :]   (W[0] == 0, so the
// X!=0 mask in the reference is a no-op on the value; we gather row 0 freely)
// X: (64,128,50) int32  -> d_in[0]
// W: (100000,128) fp32  -> d_in[1]
// out: (64,128,128) fp32
//
// One warp per output row. Lane owns one float4 (4 of 128 dims).
// Latency-limited => maximize per-thread MLP: full unroll of 50 independent
// LDG.E.128 gathers, 4 independent accumulators, ~84-reg budget.

#define NB_WORDS 50
#define EMBED    128
#define ROWS     (64 * 128)   // 8192

__global__ __launch_bounds__(256, 3) void bag_embedding_kernel(
    const int* __restrict__ X,
    const float4* __restrict__ W4,   // W viewed as rows of 32 float4
    float4* __restrict__ out4)
{
    const int warp_id = (blockIdx.x * blockDim.x + threadIdx.x) >> 5;
    const int lane    = threadIdx.x & 31;
    if (warp_id >= ROWS) return;

    const int* __restrict__ xp = X + warp_id * NB_WORDS;

    // Hoist all 50 indices (warp-uniform, L1-broadcast, line-sequential).
    int idx[NB_WORDS];
    #pragma unroll
    for (int k = 0; k < NB_WORDS; ++k) idx[k] = __ldg(xp + k);

    // 4 independent accumulator chains -> loads aren't serialized on FADDs.
    float4 a0 = make_float4(0.f, 0.f, 0.f, 0.f);
    float4 a1 = make_float4(0.f, 0.f, 0.f, 0.f);
    float4 a2 = make_float4(0.f, 0.f, 0.f, 0.f);
    float4 a3 = make_float4(0.f, 0.f, 0.f, 0.f);

    #pragma unroll
    for (int k = 0; k < NB_WORDS; k += 2) {
        // Unconditional gathers: row 0 is all zeros, adding it is a no-op.
        const float4 v0 = __ldg(W4 + (size_t)idx[k]     * (EMBED / 4) + lane);
        const float4 v1 = (k + 1 < NB_WORDS)
            ? __ldg(W4 + (size_t)idx[k + 1] * (EMBED / 4) + lane)
            : make_float4(0.f, 0.f, 0.f, 0.f);

        a0.x += v0.x; a0.y += v0.y; a0.z += v0.z; a0.w += v0.w;
        a1.x += v1.x; a1.y += v1.y; a1.z += v1.z; a1.w += v1.w;
        // rotate chains every other pair to keep 4 chains busy
        float4 t = a0; a0 = a2; a2 = t;
        t = a1; a1 = a3; a3 = t;
    }

    float4 acc;
    acc.x = (a0.x + a1.x) + (a2.x + a3.x);
    acc.y = (a0.y + a1.y) + (a2.y + a3.y);
    acc.z = (a0.z + a1.z) + (a2.z + a3.z);
    acc.w = (a0.w + a1.w) + (a2.w + a3.w);

    out4[(size_t)warp_id * (EMBED / 4) + lane] = acc;
}

extern "C" void kernel_launch(void* const* d_in, const int* in_sizes, int n_in,
                              void* d_out, int out_size)
{
    const int*    X = (const int*)d_in[0];
    const float4* W = (const float4*)d_in[1];
    float4*     out = (float4*)d_out;

    const int threads = 256;                 // 8 warps/block
    const int blocks  = (ROWS * 32) / threads; // 1024 blocks
    bag_embedding_kernel<<<blocks, threads>>>(X, W, out);
}

// round 4
// speedup vs baseline: 1.7438x; 1.2163x over previous
#include <cuda_runtime.h>
#include <stdint.h>

// BagEmbedding: out[b,l,:] = sum_{k<50} W[X[b,l,k], :]   (W[0]==0, so the
// reference's X!=0 mask is a value no-op; gathering row 0 is harmless)
// X: (64,128,50) int32  -> d_in[0]
// W: (100000,128) fp32  -> d_in[1]
// out: (64,128,128) fp32
//
// One warp per output row, 8 rows per 256-thread block.
// Indices are block-staged into SMEM (coalesced) so the gather loop issues
// ONLY the 50 LDG.128 gathers on the global path; index reads are uniform
// LDS broadcasts. Registers freed from the index array go to in-flight
// gather buffers (higher MLP). 4 independent accumulator chains.

#define NB_WORDS 50
#define EMBED    128
#define ROWS     (64 * 128)   // 8192
#define WARPS_PER_BLOCK 8
#define IDX_PER_BLOCK (WARPS_PER_BLOCK * NB_WORDS)   // 400

__global__ __launch_bounds__(256, 3) void bag_embedding_kernel(
    const int* __restrict__ X,
    const float4* __restrict__ W4,   // W as rows of 32 float4
    float4* __restrict__ out4)
{
    __shared__ int sidx[IDX_PER_BLOCK];

    const int tid  = threadIdx.x;
    const int warp = tid >> 5;
    const int lane = tid & 31;

    // ── Stage this block's 400 indices into SMEM, coalesced ──
    const int* __restrict__ xblk = X + (size_t)blockIdx.x * IDX_PER_BLOCK;
    #pragma unroll
    for (int i = tid; i < IDX_PER_BLOCK; i += 256)
        sidx[i] = xblk[i];
    __syncthreads();

    const int* __restrict__ srow = sidx + warp * NB_WORDS;

    // ── 50 independent gathers, 4 accumulator chains ──
    float4 a0 = make_float4(0.f, 0.f, 0.f, 0.f);
    float4 a1 = make_float4(0.f, 0.f, 0.f, 0.f);
    float4 a2 = make_float4(0.f, 0.f, 0.f, 0.f);
    float4 a3 = make_float4(0.f, 0.f, 0.f, 0.f);

    #pragma unroll
    for (int k = 0; k < NB_WORDS; k += 4) {
        const int i0 = srow[k];
        const int i1 = srow[k + 1];
        const float4 v0 = __ldg(W4 + (size_t)i0 * (EMBED / 4) + lane);
        const float4 v1 = __ldg(W4 + (size_t)i1 * (EMBED / 4) + lane);

        float4 v2 = make_float4(0.f, 0.f, 0.f, 0.f);
        float4 v3 = make_float4(0.f, 0.f, 0.f, 0.f);
        if (k + 2 < NB_WORDS) {
            const int i2 = srow[k + 2];
            v2 = __ldg(W4 + (size_t)i2 * (EMBED / 4) + lane);
        }
        if (k + 3 < NB_WORDS) {
            const int i3 = srow[k + 3];
            v3 = __ldg(W4 + (size_t)i3 * (EMBED / 4) + lane);
        }

        a0.x += v0.x; a0.y += v0.y; a0.z += v0.z; a0.w += v0.w;
        a1.x += v1.x; a1.y += v1.y; a1.z += v1.z; a1.w += v1.w;
        a2.x += v2.x; a2.y += v2.y; a2.z += v2.z; a2.w += v2.w;
        a3.x += v3.x; a3.y += v3.y; a3.z += v3.z; a3.w += v3.w;
    }

    float4 acc;
    acc.x = (a0.x + a1.x) + (a2.x + a3.x);
    acc.y = (a0.y + a1.y) + (a2.y + a3.y);
    acc.z = (a0.z + a1.z) + (a2.z + a3.z);
    acc.w = (a0.w + a1.w) + (a2.w + a3.w);

    const int row = blockIdx.x * WARPS_PER_BLOCK + warp;
    out4[(size_t)row * (EMBED / 4) + lane] = acc;
}

extern "C" void kernel_launch(void* const* d_in, const int* in_sizes, int n_in,
                              void* d_out, int out_size)
{
    const int*    X = (const int*)d_in[0];
    const float4* W = (const float4*)d_in[1];
    float4*     out = (float4*)d_out;

    const int threads = 256;                       // 8 warps = 8 rows
    const int blocks  = ROWS / WARPS_PER_BLOCK;    // 1024
    bag_embedding_kernel<<<blocks, threads>>>(X, W, out);
}